// round 8
// baseline (speedup 1.0000x reference)
#include <cuda_runtime.h>

// ---------------------------------------------------------------------------
// FCOS decoder head, fp32 SIMT implicit-GEMM implementation.
//   5 FPN levels (128^2 .. 8^2), batch 4, C=256.
//   Each head: 4 x [conv3x3 -> BN(scale,bias) -> ReLU] -> 1x1 conv (+bias).
//   cls head: 80 ch out. reg head: 5 ch out -> ch0 = centerness,
//   ch1..4 = max(raw * stride, 0).
// BN scale is folded into the 3x3 weights by a per-launch fold/transpose
// kernel that also lays weights out as [(c*9+t)][k] for coalesced staging.
// ---------------------------------------------------------------------------

#define FPN_LEVELS 5
#define CH 256

// Scratch (device globals: allocation-free, graph-capturable).
__device__ float g_bufA[4 * 256 * 128 * 128];   // 64 MB ping
__device__ float g_bufB[4 * 256 * 128 * 128];   // 64 MB pong
__device__ float g_wt[2 * 4 * 2304 * 256];      // folded weights, 18 MB
                                                // layout: [head][layer][(c*9+t)][k]

// ---------------------------------------------------------------------------
// Fold BN scale into 3x3 weights + transpose to [(c*9+t)][k].
// total elements = 2 heads * 4 layers * 256c * 9t * 256k = 4,718,592
// ---------------------------------------------------------------------------
__global__ void fold_weights_kernel(const float* __restrict__ cls_w,
                                    const float* __restrict__ cls_s,
                                    const float* __restrict__ reg_w,
                                    const float* __restrict__ reg_s) {
    int o = blockIdx.x * 256 + threadIdx.x;     // exact grid, no guard needed
    int k    = o & 255;
    int rest = o >> 8;                          // ((head*4+L)*256 + c)*9 + t
    int t    = rest % 9;
    int q    = rest / 9;                        // (head*4+L)*256 + c
    int c    = q & 255;
    int q2   = q >> 8;                          // head*4 + L
    int L    = q2 & 3;
    int head = q2 >> 2;
    const float* w = head ? reg_w : cls_w;
    const float* s = head ? reg_s : cls_s;
    // source layout: [L][k][c][3][3]
    g_wt[o] = w[((L * 256 + k) * 256 + c) * 9 + t] * s[L * 256 + k];
}

// ---------------------------------------------------------------------------
// Big conv3x3: CTA tile = 128 out-ch x (8 rows x 16 cols) spatial.
// 256 threads: 16 k-threads (8 ch each) x 16 spatial threads (1 row x 8 cols).
// Used for levels 0,1 (H,W multiples of 16/8 -> no output guards needed).
// ---------------------------------------------------------------------------
__global__ __launch_bounds__(256, 2)
void conv3x3_big(const float* __restrict__ in, float* __restrict__ out,
                 const float* __restrict__ wt,      // layer base: [(c*9+t)*256 + k]
                 const float* __restrict__ bias,    // 256
                 int H, int W) {
    __shared__ __align__(16) float in_s[8 * 10 * 20];   // 8c x 10y x 18x (pad 20)
    __shared__ __align__(16) float w_s[72 * 128];       // [(cc*9+t)][k]

    const int tid = threadIdx.x;
    const int st  = tid & 15;
    const int kt  = tid >> 4;            // 0..15, 8 out-ch each
    const int r   = st & 7;              // output row within tile
    const int c2  = st >> 3;             // 0/1 -> x offset 0 or 8
    const int x0  = blockIdx.x * 16;
    const int y0  = blockIdx.y * 8;
    const int n   = blockIdx.z >> 1;
    const int k0  = (blockIdx.z & 1) * 128;
    const float* inb = in + ((size_t)n * CH) * H * W;

    float acc[8][8];
#pragma unroll
    for (int a = 0; a < 8; ++a)
#pragma unroll
        for (int b = 0; b < 8; ++b) acc[a][b] = 0.f;

    for (int c0 = 0; c0 < CH; c0 += 8) {
        // stage input patch 8c x 10y x 18x (with halo + zero padding)
        for (int i = tid; i < 1440; i += 256) {
            int x  = i % 18;
            int yq = i / 18;
            int y  = yq % 10;
            int cc = yq / 10;
            int iy = y0 - 1 + y;
            int ix = x0 - 1 + x;
            float v = 0.f;
            if ((unsigned)iy < (unsigned)H && (unsigned)ix < (unsigned)W)
                v = inb[((c0 + cc) * H + iy) * W + ix];
            in_s[cc * 200 + y * 20 + x] = v;
        }
        // stage weights 8c x 9t x 128k  (coalesced LDG, conflict-free STS)
        {
            const float* wp = wt + (size_t)(c0 * 9) * 256 + k0;
            for (int j = tid; j < 9216; j += 256) {
                int k = j & 127;
                int q = j >> 7;          // cc*9 + t
                w_s[j] = wp[q * 256 + k];
            }
        }
        __syncthreads();

#pragma unroll 2
        for (int cc = 0; cc < 8; ++cc) {
#pragma unroll
            for (int dy = 0; dy < 3; ++dy) {
                const float* rowp = &in_s[cc * 200 + (r + dy) * 20 + c2 * 8];
                float rr[10];
                float4 a0 = *(const float4*)rowp;
                float4 a1 = *(const float4*)(rowp + 4);
                rr[0] = a0.x; rr[1] = a0.y; rr[2] = a0.z; rr[3] = a0.w;
                rr[4] = a1.x; rr[5] = a1.y; rr[6] = a1.z; rr[7] = a1.w;
                rr[8] = rowp[8]; rr[9] = rowp[9];
                const float* wrow = &w_s[(cc * 9 + dy * 3) * 128 + kt * 8];
#pragma unroll
                for (int dx = 0; dx < 3; ++dx) {
                    float4 w0 = *(const float4*)(wrow + dx * 128);
                    float4 w1 = *(const float4*)(wrow + dx * 128 + 4);
                    float wk[8] = {w0.x, w0.y, w0.z, w0.w, w1.x, w1.y, w1.z, w1.w};
#pragma unroll
                    for (int xi = 0; xi < 8; ++xi)
#pragma unroll
                        for (int ki = 0; ki < 8; ++ki)
                            acc[xi][ki] = fmaf(rr[xi + dx], wk[ki], acc[xi][ki]);
                }
            }
        }
        __syncthreads();
    }

    const int gy  = y0 + r;
    const int gxb = x0 + c2 * 8;
#pragma unroll
    for (int ki = 0; ki < 8; ++ki) {
        int k = k0 + kt * 8 + ki;
        float bv = bias[k];
        float4 o0, o1;
        o0.x = fmaxf(acc[0][ki] + bv, 0.f);
        o0.y = fmaxf(acc[1][ki] + bv, 0.f);
        o0.z = fmaxf(acc[2][ki] + bv, 0.f);
        o0.w = fmaxf(acc[3][ki] + bv, 0.f);
        o1.x = fmaxf(acc[4][ki] + bv, 0.f);
        o1.y = fmaxf(acc[5][ki] + bv, 0.f);
        o1.z = fmaxf(acc[6][ki] + bv, 0.f);
        o1.w = fmaxf(acc[7][ki] + bv, 0.f);
        float* op = out + ((size_t)(n * CH + k) * H + gy) * W + gxb;
        *(float4*)op       = o0;
        *(float4*)(op + 4) = o1;
    }
}

// ---------------------------------------------------------------------------
// Small conv3x3: CTA tile = 64 out-ch x (8x8) spatial, 4x4 register tile.
// Used for levels 2..4 (H,W multiples of 8) to keep grids >= 16 CTAs.
// ---------------------------------------------------------------------------
__global__ __launch_bounds__(256, 2)
void conv3x3_small(const float* __restrict__ in, float* __restrict__ out,
                   const float* __restrict__ wt,
                   const float* __restrict__ bias,
                   int H, int W) {
    __shared__ __align__(16) float in_s[8 * 10 * 12];   // 8c x 10y x 10x (pad 12)
    __shared__ __align__(16) float w_s[72 * 64];

    const int tid = threadIdx.x;
    const int st  = tid & 15;
    const int kt  = tid >> 4;            // 0..15, 4 out-ch each
    const int r   = st & 7;
    const int c2  = st >> 3;             // x offset 0 or 4
    const int x0  = blockIdx.x * 8;
    const int y0  = blockIdx.y * 8;
    const int n   = blockIdx.z >> 2;
    const int k0  = (blockIdx.z & 3) * 64;
    const float* inb = in + ((size_t)n * CH) * H * W;

    float acc[4][4];
#pragma unroll
    for (int a = 0; a < 4; ++a)
#pragma unroll
        for (int b = 0; b < 4; ++b) acc[a][b] = 0.f;

    for (int c0 = 0; c0 < CH; c0 += 8) {
        for (int i = tid; i < 800; i += 256) {
            int x  = i % 10;
            int yq = i / 10;
            int y  = yq % 10;
            int cc = yq / 10;
            int iy = y0 - 1 + y;
            int ix = x0 - 1 + x;
            float v = 0.f;
            if ((unsigned)iy < (unsigned)H && (unsigned)ix < (unsigned)W)
                v = inb[((c0 + cc) * H + iy) * W + ix];
            in_s[cc * 120 + y * 12 + x] = v;
        }
        {
            const float* wp = wt + (size_t)(c0 * 9) * 256 + k0;
            for (int j = tid; j < 4608; j += 256) {
                int k = j & 63;
                int q = j >> 6;
                w_s[j] = wp[q * 256 + k];
            }
        }
        __syncthreads();

#pragma unroll
        for (int cc = 0; cc < 8; ++cc) {
#pragma unroll
            for (int dy = 0; dy < 3; ++dy) {
                const float* rowp = &in_s[cc * 120 + (r + dy) * 12 + c2 * 4];
                float rr[6];
                float4 a0 = *(const float4*)rowp;
                rr[0] = a0.x; rr[1] = a0.y; rr[2] = a0.z; rr[3] = a0.w;
                rr[4] = rowp[4]; rr[5] = rowp[5];
                const float* wrow = &w_s[(cc * 9 + dy * 3) * 64 + kt * 4];
#pragma unroll
                for (int dx = 0; dx < 3; ++dx) {
                    float4 w0 = *(const float4*)(wrow + dx * 64);
                    float wk[4] = {w0.x, w0.y, w0.z, w0.w};
#pragma unroll
                    for (int xi = 0; xi < 4; ++xi)
#pragma unroll
                        for (int ki = 0; ki < 4; ++ki)
                            acc[xi][ki] = fmaf(rr[xi + dx], wk[ki], acc[xi][ki]);
                }
            }
        }
        __syncthreads();
    }

    const int gy  = y0 + r;
    const int gxb = x0 + c2 * 4;
#pragma unroll
    for (int ki = 0; ki < 4; ++ki) {
        int k = k0 + kt * 4 + ki;
        float bv = bias[k];
        float4 o0;
        o0.x = fmaxf(acc[0][ki] + bv, 0.f);
        o0.y = fmaxf(acc[1][ki] + bv, 0.f);
        o0.z = fmaxf(acc[2][ki] + bv, 0.f);
        o0.w = fmaxf(acc[3][ki] + bv, 0.f);
        *(float4*)(out + ((size_t)(n * CH + k) * H + gy) * W + gxb) = o0;
    }
}

// ---------------------------------------------------------------------------
// cls final: 1x1 conv 256 -> 80, + bias. One thread per spatial position,
// 80 accumulators in registers; weights staged in 64-channel smem chunks.
// ---------------------------------------------------------------------------
__global__ __launch_bounds__(256)
void final_cls_kernel(const float* __restrict__ x, const float* __restrict__ w,
                      const float* __restrict__ b, float* __restrict__ out,
                      int HW) {
    __shared__ __align__(16) float ws[64 * 84];   // [cc][k], pad 84
    __shared__ float bs[80];
    const int tid = threadIdx.x;
    const int p   = blockIdx.x * 256 + tid;       // grid exact: 4*HW % 256 == 0
    const int n   = p / HW;
    const int hw  = p % HW;
    const float* xb = x + ((size_t)n * CH) * HW + hw;
    if (tid < 80) bs[tid] = b[tid];

    float acc[80];
#pragma unroll
    for (int k = 0; k < 80; ++k) acc[k] = 0.f;

    for (int c0 = 0; c0 < CH; c0 += 64) {
        __syncthreads();
        for (int j = tid; j < 5120; j += 256) {
            int cc = j & 63;
            int k  = j >> 6;
            ws[cc * 84 + k] = w[k * 256 + c0 + cc];
        }
        __syncthreads();
#pragma unroll 4
        for (int cc = 0; cc < 64; ++cc) {
            float xv = xb[(c0 + cc) * HW];
            const float* wr = &ws[cc * 84];
#pragma unroll
            for (int k = 0; k < 80; k += 4) {
                float4 wv = *(const float4*)(wr + k);
                acc[k]     = fmaf(xv, wv.x, acc[k]);
                acc[k + 1] = fmaf(xv, wv.y, acc[k + 1]);
                acc[k + 2] = fmaf(xv, wv.z, acc[k + 2]);
                acc[k + 3] = fmaf(xv, wv.w, acc[k + 3]);
            }
        }
    }
    float* ob = out + ((size_t)n * 80) * HW + hw;
#pragma unroll
    for (int k = 0; k < 80; ++k) ob[(size_t)k * HW] = acc[k] + bs[k];
}

// ---------------------------------------------------------------------------
// reg final: 1x1 conv 256 -> 5, ch0 -> centerness (raw), ch1..4 -> reg with
// *stride then ReLU.
// ---------------------------------------------------------------------------
__global__ __launch_bounds__(256)
void final_reg_kernel(const float* __restrict__ x, const float* __restrict__ w,
                      const float* __restrict__ b, float* __restrict__ out_reg,
                      float* __restrict__ out_ctr, int HW, float sc) {
    __shared__ float ws[256 * 5];
    const int tid = threadIdx.x;
    for (int j = tid; j < 1280; j += 256) {
        int cc = j % 256;
        int k  = j / 256;
        ws[cc * 5 + k] = w[k * 256 + cc];
    }
    __syncthreads();
    const int p  = blockIdx.x * 256 + tid;
    const int n  = p / HW;
    const int hw = p % HW;
    const float* xb = x + ((size_t)n * CH) * HW + hw;
    float a0 = 0.f, a1 = 0.f, a2 = 0.f, a3 = 0.f, a4 = 0.f;
#pragma unroll 4
    for (int c = 0; c < CH; ++c) {
        float xv = xb[c * HW];
        const float* wr = &ws[c * 5];
        a0 = fmaf(xv, wr[0], a0);
        a1 = fmaf(xv, wr[1], a1);
        a2 = fmaf(xv, wr[2], a2);
        a3 = fmaf(xv, wr[3], a3);
        a4 = fmaf(xv, wr[4], a4);
    }
    out_ctr[(size_t)n * HW + hw] = a0 + b[0];
    out_reg[((size_t)n * 4 + 0) * HW + hw] = fmaxf((a1 + b[1]) * sc, 0.f);
    out_reg[((size_t)n * 4 + 1) * HW + hw] = fmaxf((a2 + b[2]) * sc, 0.f);
    out_reg[((size_t)n * 4 + 2) * HW + hw] = fmaxf((a3 + b[3]) * sc, 0.f);
    out_reg[((size_t)n * 4 + 3) * HW + hw] = fmaxf((a4 + b[4]) * sc, 0.f);
}

// ---------------------------------------------------------------------------
// Host launcher (graph-capturable: kernel launches only).
// ---------------------------------------------------------------------------
extern "C" void kernel_launch(void* const* d_in, const int* in_sizes, int n_in,
                              void* d_out, int out_size) {
    const float* fpn[5];
    for (int i = 0; i < 5; ++i) fpn[i] = (const float*)d_in[i];
    const float* cls_conv_w   = (const float*)d_in[5];
    const float* cls_bn_scale = (const float*)d_in[6];
    const float* cls_bn_bias  = (const float*)d_in[7];
    const float* cls_final_w  = (const float*)d_in[8];
    const float* cls_final_b  = (const float*)d_in[9];
    const float* reg_conv_w   = (const float*)d_in[10];
    const float* reg_bn_scale = (const float*)d_in[11];
    const float* reg_bn_bias  = (const float*)d_in[12];
    const float* reg_final_w  = (const float*)d_in[13];
    const float* reg_final_b  = (const float*)d_in[14];
    float* out = (float*)d_out;

    float *bufA, *bufB, *wt;
    cudaGetSymbolAddress((void**)&bufA, g_bufA);
    cudaGetSymbolAddress((void**)&bufB, g_bufB);
    cudaGetSymbolAddress((void**)&wt,   g_wt);

    // Fold BN scale into 3x3 weights + transpose. 4,718,592 / 256 = 18,432 CTAs.
    fold_weights_kernel<<<18432, 256>>>(cls_conv_w, cls_bn_scale,
                                        reg_conv_w, reg_bn_scale);

    const int   Hs[5]  = {128, 64, 32, 16, 8};
    const float scs[5] = {8.f, 16.f, 32.f, 64.f, 128.f};

    size_t cls_off[5], reg_off[5], ctr_off[5];
    size_t a = 0;
    for (int l = 0; l < 5; ++l) { cls_off[l] = a; a += (size_t)4 * 80 * Hs[l] * Hs[l]; }
    for (int l = 0; l < 5; ++l) { reg_off[l] = a; a += (size_t)4 * 4  * Hs[l] * Hs[l]; }
    for (int l = 0; l < 5; ++l) { ctr_off[l] = a; a += (size_t)4 * 1  * Hs[l] * Hs[l]; }

    for (int l = 0; l < 5; ++l) {
        const int H = Hs[l], W = Hs[l], HW = H * W;
        for (int head = 0; head < 2; ++head) {
            const float* bias_base = head ? reg_bn_bias : cls_bn_bias;
            float* bufs[2] = {bufA, bufB};
            for (int L = 0; L < 4; ++L) {
                const float* src = (L == 0) ? fpn[l] : bufs[(L + 1) & 1];
                float*       dst = bufs[L & 1];
                const float* wL  = wt + (size_t)(head * 4 + L) * 2304 * 256;
                if (l < 2) {
                    dim3 grid(W / 16, H / 8, 8);     // 4 batch x 2 k-tiles
                    conv3x3_big<<<grid, 256>>>(src, dst, wL, bias_base + L * 256, H, W);
                } else {
                    dim3 grid(W / 8, H / 8, 16);     // 4 batch x 4 k-tiles
                    conv3x3_small<<<grid, 256>>>(src, dst, wL, bias_base + L * 256, H, W);
                }
            }
            const int PB = (4 * HW) / 256;           // always exact
            if (head == 0)
                final_cls_kernel<<<PB, 256>>>(bufB, cls_final_w, cls_final_b,
                                              out + cls_off[l], HW);
            else
                final_reg_kernel<<<PB, 256>>>(bufB, reg_final_w, reg_final_b,
                                              out + reg_off[l], out + ctr_off[l],
                                              HW, scs[l]);
        }
    }
}

// round 9
// speedup vs baseline: 1.1259x; 1.1259x over previous
#include <cuda_runtime.h>

// ---------------------------------------------------------------------------
// FCOS decoder head, fp32 SIMT implicit-GEMM implementation, packed-f32x2 core.
//   5 FPN levels (128^2 .. 8^2), batch 4, C=256.
//   Each head: 4 x [conv3x3 -> BN(scale,bias) -> ReLU] -> 1x1 conv (+bias).
//   cls head: 80 ch out. reg head: 5 ch out -> ch0 = centerness,
//   ch1..4 = max(raw * stride, 0).
// Inner loops use fma.rn.f32x2 (FFMA2) — 2 fp32 FMAs per instruction, the only
// way to reach the full 256 FLOP/cyc/SM fp32 rate on sm_103a (ptxas never
// emits it from C++). Accumulators are paired over adjacent output channels;
// weight pairs come straight out of SMEM as 64-bit register pairs.
// ---------------------------------------------------------------------------

#define FPN_LEVELS 5
#define CH 256

typedef unsigned long long u64;

__device__ __forceinline__ void ffma2(u64& d, u64 a, u64 b) {
    asm("fma.rn.f32x2 %0, %1, %2, %0;" : "+l"(d) : "l"(a), "l"(b));
}
__device__ __forceinline__ u64 pack2(float x) {
    unsigned xi = __float_as_uint(x);
    u64 r;
    asm("mov.b64 %0, {%1, %1};" : "=l"(r) : "r"(xi));
    return r;
}
__device__ __forceinline__ float lane(u64 v, int h) {
    float2 f = *reinterpret_cast<const float2*>(&v);
    return h ? f.y : f.x;
}

// Scratch (device globals: allocation-free, graph-capturable).
__device__ float g_bufA[4 * 256 * 128 * 128];   // 64 MB ping
__device__ float g_bufB[4 * 256 * 128 * 128];   // 64 MB pong
__device__ float g_wt[2 * 4 * 2304 * 256];      // folded weights, 18 MB
                                                // layout: [head][layer][(c*9+t)][k]

// ---------------------------------------------------------------------------
// Fold BN scale into 3x3 weights + transpose to [(c*9+t)][k].
// total elements = 2 heads * 4 layers * 256c * 9t * 256k = 4,718,592
// ---------------------------------------------------------------------------
__global__ void fold_weights_kernel(const float* __restrict__ cls_w,
                                    const float* __restrict__ cls_s,
                                    const float* __restrict__ reg_w,
                                    const float* __restrict__ reg_s) {
    int o = blockIdx.x * 256 + threadIdx.x;     // exact grid, no guard needed
    int k    = o & 255;
    int rest = o >> 8;                          // ((head*4+L)*256 + c)*9 + t
    int t    = rest % 9;
    int q    = rest / 9;                        // (head*4+L)*256 + c
    int c    = q & 255;
    int q2   = q >> 8;                          // head*4 + L
    int L    = q2 & 3;
    int head = q2 >> 2;
    const float* w = head ? reg_w : cls_w;
    const float* s = head ? reg_s : cls_s;
    // source layout: [L][k][c][3][3]
    g_wt[o] = w[((L * 256 + k) * 256 + c) * 9 + t] * s[L * 256 + k];
}

// ---------------------------------------------------------------------------
// Big conv3x3: CTA tile = 128 out-ch x (8 rows x 16 cols) spatial.
// 256 threads: 16 k-threads (8 ch each) x 16 spatial threads (1 row x 8 cols).
// Per-thread tile: 8 spatial x 8 out-ch, held as 8x4 f32x2 pairs.
// Used for levels 0,1 (H,W multiples of 16/8 -> no output guards needed).
// ---------------------------------------------------------------------------
__global__ __launch_bounds__(256, 2)
void conv3x3_big(const float* __restrict__ in, float* __restrict__ out,
                 const float* __restrict__ wt,      // layer base: [(c*9+t)*256 + k]
                 const float* __restrict__ bias,    // 256
                 int H, int W) {
    __shared__ __align__(16) float in_s[8 * 10 * 20];   // 8c x 10y x 18x (pad 20)
    __shared__ __align__(16) float w_s[72 * 128];       // [(cc*9+t)][k]

    const int tid = threadIdx.x;
    const int st  = tid & 15;
    const int kt  = tid >> 4;            // 0..15, 8 out-ch each
    const int r   = st & 7;              // output row within tile
    const int c2  = st >> 3;             // 0/1 -> x offset 0 or 8
    const int x0  = blockIdx.x * 16;
    const int y0  = blockIdx.y * 8;
    const int n   = blockIdx.z >> 1;
    const int k0  = (blockIdx.z & 1) * 128;
    const float* inb = in + ((size_t)n * CH) * H * W;

    u64 acc[8][4];                        // [spatial xi][k-pair]
#pragma unroll
    for (int a = 0; a < 8; ++a)
#pragma unroll
        for (int b = 0; b < 4; ++b) acc[a][b] = 0ull;

    for (int c0 = 0; c0 < CH; c0 += 8) {
        // stage input patch 8c x 10y x 18x (with halo + zero padding)
        for (int i = tid; i < 1440; i += 256) {
            int x  = i % 18;
            int yq = i / 18;
            int y  = yq % 10;
            int cc = yq / 10;
            int iy = y0 - 1 + y;
            int ix = x0 - 1 + x;
            float v = 0.f;
            if ((unsigned)iy < (unsigned)H && (unsigned)ix < (unsigned)W)
                v = inb[((c0 + cc) * H + iy) * W + ix];
            in_s[cc * 200 + y * 20 + x] = v;
        }
        // stage weights 8c x 9t x 128k  (coalesced LDG, conflict-free STS)
        {
            const float* wp = wt + (size_t)(c0 * 9) * 256 + k0;
            for (int j = tid; j < 9216; j += 256) {
                int k = j & 127;
                int q = j >> 7;          // cc*9 + t
                w_s[j] = wp[q * 256 + k];
            }
        }
        __syncthreads();

#pragma unroll 2
        for (int cc = 0; cc < 8; ++cc) {
#pragma unroll
            for (int dy = 0; dy < 3; ++dy) {
                const float* rowp = &in_s[cc * 200 + (r + dy) * 20 + c2 * 8];
                float4 a0 = *(const float4*)rowp;
                float4 a1 = *(const float4*)(rowp + 4);
                u64 rp[10];
                rp[0] = pack2(a0.x); rp[1] = pack2(a0.y);
                rp[2] = pack2(a0.z); rp[3] = pack2(a0.w);
                rp[4] = pack2(a1.x); rp[5] = pack2(a1.y);
                rp[6] = pack2(a1.z); rp[7] = pack2(a1.w);
                rp[8] = pack2(rowp[8]); rp[9] = pack2(rowp[9]);
                const float* wrow = &w_s[(cc * 9 + dy * 3) * 128 + kt * 8];
#pragma unroll
                for (int dx = 0; dx < 3; ++dx) {
                    ulonglong2 wv0 = *(const ulonglong2*)(wrow + dx * 128);
                    ulonglong2 wv1 = *(const ulonglong2*)(wrow + dx * 128 + 4);
                    const u64 w0 = wv0.x, w1 = wv0.y, w2 = wv1.x, w3 = wv1.y;
#pragma unroll
                    for (int xi = 0; xi < 8; ++xi) {
                        u64 xv = rp[xi + dx];
                        ffma2(acc[xi][0], xv, w0);
                        ffma2(acc[xi][1], xv, w1);
                        ffma2(acc[xi][2], xv, w2);
                        ffma2(acc[xi][3], xv, w3);
                    }
                }
            }
        }
        __syncthreads();
    }

    const int gy  = y0 + r;
    const int gxb = x0 + c2 * 8;
#pragma unroll
    for (int kp = 0; kp < 4; ++kp) {
#pragma unroll
        for (int h = 0; h < 2; ++h) {
            int k = k0 + kt * 8 + kp * 2 + h;
            float bv = bias[k];
            float4 o0, o1;
            o0.x = fmaxf(lane(acc[0][kp], h) + bv, 0.f);
            o0.y = fmaxf(lane(acc[1][kp], h) + bv, 0.f);
            o0.z = fmaxf(lane(acc[2][kp], h) + bv, 0.f);
            o0.w = fmaxf(lane(acc[3][kp], h) + bv, 0.f);
            o1.x = fmaxf(lane(acc[4][kp], h) + bv, 0.f);
            o1.y = fmaxf(lane(acc[5][kp], h) + bv, 0.f);
            o1.z = fmaxf(lane(acc[6][kp], h) + bv, 0.f);
            o1.w = fmaxf(lane(acc[7][kp], h) + bv, 0.f);
            float* op = out + ((size_t)(n * CH + k) * H + gy) * W + gxb;
            *(float4*)op       = o0;
            *(float4*)(op + 4) = o1;
        }
    }
}

// ---------------------------------------------------------------------------
// Small conv3x3: CTA tile = 64 out-ch x (8x8) spatial, 4 spatial x 2 k-pairs.
// Used for levels 2..4 (H,W multiples of 8) to keep grids >= 16 CTAs.
// ---------------------------------------------------------------------------
__global__ __launch_bounds__(256, 2)
void conv3x3_small(const float* __restrict__ in, float* __restrict__ out,
                   const float* __restrict__ wt,
                   const float* __restrict__ bias,
                   int H, int W) {
    __shared__ __align__(16) float in_s[8 * 10 * 12];   // 8c x 10y x 10x (pad 12)
    __shared__ __align__(16) float w_s[72 * 64];

    const int tid = threadIdx.x;
    const int st  = tid & 15;
    const int kt  = tid >> 4;            // 0..15, 4 out-ch each
    const int r   = st & 7;
    const int c2  = st >> 3;             // x offset 0 or 4
    const int x0  = blockIdx.x * 8;
    const int y0  = blockIdx.y * 8;
    const int n   = blockIdx.z >> 2;
    const int k0  = (blockIdx.z & 3) * 64;
    const float* inb = in + ((size_t)n * CH) * H * W;

    u64 acc[4][2];
#pragma unroll
    for (int a = 0; a < 4; ++a)
#pragma unroll
        for (int b = 0; b < 2; ++b) acc[a][b] = 0ull;

    for (int c0 = 0; c0 < CH; c0 += 8) {
        for (int i = tid; i < 800; i += 256) {
            int x  = i % 10;
            int yq = i / 10;
            int y  = yq % 10;
            int cc = yq / 10;
            int iy = y0 - 1 + y;
            int ix = x0 - 1 + x;
            float v = 0.f;
            if ((unsigned)iy < (unsigned)H && (unsigned)ix < (unsigned)W)
                v = inb[((c0 + cc) * H + iy) * W + ix];
            in_s[cc * 120 + y * 12 + x] = v;
        }
        {
            const float* wp = wt + (size_t)(c0 * 9) * 256 + k0;
            for (int j = tid; j < 4608; j += 256) {
                int k = j & 63;
                int q = j >> 6;
                w_s[j] = wp[q * 256 + k];
            }
        }
        __syncthreads();

#pragma unroll
        for (int cc = 0; cc < 8; ++cc) {
#pragma unroll
            for (int dy = 0; dy < 3; ++dy) {
                const float* rowp = &in_s[cc * 120 + (r + dy) * 12 + c2 * 4];
                float4 a0 = *(const float4*)rowp;
                u64 rp[6];
                rp[0] = pack2(a0.x); rp[1] = pack2(a0.y);
                rp[2] = pack2(a0.z); rp[3] = pack2(a0.w);
                rp[4] = pack2(rowp[4]); rp[5] = pack2(rowp[5]);
                const float* wrow = &w_s[(cc * 9 + dy * 3) * 64 + kt * 4];
#pragma unroll
                for (int dx = 0; dx < 3; ++dx) {
                    ulonglong2 wv = *(const ulonglong2*)(wrow + dx * 64);
                    const u64 w0 = wv.x, w1 = wv.y;
#pragma unroll
                    for (int xi = 0; xi < 4; ++xi) {
                        u64 xv = rp[xi + dx];
                        ffma2(acc[xi][0], xv, w0);
                        ffma2(acc[xi][1], xv, w1);
                    }
                }
            }
        }
        __syncthreads();
    }

    const int gy  = y0 + r;
    const int gxb = x0 + c2 * 4;
#pragma unroll
    for (int kp = 0; kp < 2; ++kp) {
#pragma unroll
        for (int h = 0; h < 2; ++h) {
            int k = k0 + kt * 4 + kp * 2 + h;
            float bv = bias[k];
            float4 o0;
            o0.x = fmaxf(lane(acc[0][kp], h) + bv, 0.f);
            o0.y = fmaxf(lane(acc[1][kp], h) + bv, 0.f);
            o0.z = fmaxf(lane(acc[2][kp], h) + bv, 0.f);
            o0.w = fmaxf(lane(acc[3][kp], h) + bv, 0.f);
            *(float4*)(out + ((size_t)(n * CH + k) * H + gy) * W + gxb) = o0;
        }
    }
}

// ---------------------------------------------------------------------------
// cls final: 1x1 conv 256 -> 80, + bias. One thread per spatial position,
// 80 accumulators in registers; weights staged in 64-channel smem chunks.
// ---------------------------------------------------------------------------
__global__ __launch_bounds__(256)
void final_cls_kernel(const float* __restrict__ x, const float* __restrict__ w,
                      const float* __restrict__ b, float* __restrict__ out,
                      int HW) {
    __shared__ __align__(16) float ws[64 * 84];   // [cc][k], pad 84
    __shared__ float bs[80];
    const int tid = threadIdx.x;
    const int p   = blockIdx.x * 256 + tid;       // grid exact: 4*HW % 256 == 0
    const int n   = p / HW;
    const int hw  = p % HW;
    const float* xb = x + ((size_t)n * CH) * HW + hw;
    if (tid < 80) bs[tid] = b[tid];

    float acc[80];
#pragma unroll
    for (int k = 0; k < 80; ++k) acc[k] = 0.f;

    for (int c0 = 0; c0 < CH; c0 += 64) {
        __syncthreads();
        for (int j = tid; j < 5120; j += 256) {
            int cc = j & 63;
            int k  = j >> 6;
            ws[cc * 84 + k] = w[k * 256 + c0 + cc];
        }
        __syncthreads();
#pragma unroll 4
        for (int cc = 0; cc < 64; ++cc) {
            float xv = xb[(c0 + cc) * HW];
            const float* wr = &ws[cc * 84];
#pragma unroll
            for (int k = 0; k < 80; k += 4) {
                float4 wv = *(const float4*)(wr + k);
                acc[k]     = fmaf(xv, wv.x, acc[k]);
                acc[k + 1] = fmaf(xv, wv.y, acc[k + 1]);
                acc[k + 2] = fmaf(xv, wv.z, acc[k + 2]);
                acc[k + 3] = fmaf(xv, wv.w, acc[k + 3]);
            }
        }
    }
    float* ob = out + ((size_t)n * 80) * HW + hw;
#pragma unroll
    for (int k = 0; k < 80; ++k) ob[(size_t)k * HW] = acc[k] + bs[k];
}

// ---------------------------------------------------------------------------
// reg final: 1x1 conv 256 -> 5, ch0 -> centerness (raw), ch1..4 -> reg with
// *stride then ReLU.
// ---------------------------------------------------------------------------
__global__ __launch_bounds__(256)
void final_reg_kernel(const float* __restrict__ x, const float* __restrict__ w,
                      const float* __restrict__ b, float* __restrict__ out_reg,
                      float* __restrict__ out_ctr, int HW, float sc) {
    __shared__ float ws[256 * 5];
    const int tid = threadIdx.x;
    for (int j = tid; j < 1280; j += 256) {
        int cc = j % 256;
        int k  = j / 256;
        ws[cc * 5 + k] = w[k * 256 + cc];
    }
    __syncthreads();
    const int p  = blockIdx.x * 256 + tid;
    const int n  = p / HW;
    const int hw = p % HW;
    const float* xb = x + ((size_t)n * CH) * HW + hw;
    float a0 = 0.f, a1 = 0.f, a2 = 0.f, a3 = 0.f, a4 = 0.f;
#pragma unroll 4
    for (int c = 0; c < CH; ++c) {
        float xv = xb[c * HW];
        const float* wr = &ws[c * 5];
        a0 = fmaf(xv, wr[0], a0);
        a1 = fmaf(xv, wr[1], a1);
        a2 = fmaf(xv, wr[2], a2);
        a3 = fmaf(xv, wr[3], a3);
        a4 = fmaf(xv, wr[4], a4);
    }
    out_ctr[(size_t)n * HW + hw] = a0 + b[0];
    out_reg[((size_t)n * 4 + 0) * HW + hw] = fmaxf((a1 + b[1]) * sc, 0.f);
    out_reg[((size_t)n * 4 + 1) * HW + hw] = fmaxf((a2 + b[2]) * sc, 0.f);
    out_reg[((size_t)n * 4 + 2) * HW + hw] = fmaxf((a3 + b[3]) * sc, 0.f);
    out_reg[((size_t)n * 4 + 3) * HW + hw] = fmaxf((a4 + b[4]) * sc, 0.f);
}

// ---------------------------------------------------------------------------
// Host launcher (graph-capturable: kernel launches only).
// ---------------------------------------------------------------------------
extern "C" void kernel_launch(void* const* d_in, const int* in_sizes, int n_in,
                              void* d_out, int out_size) {
    const float* fpn[5];
    for (int i = 0; i < 5; ++i) fpn[i] = (const float*)d_in[i];
    const float* cls_conv_w   = (const float*)d_in[5];
    const float* cls_bn_scale = (const float*)d_in[6];
    const float* cls_bn_bias  = (const float*)d_in[7];
    const float* cls_final_w  = (const float*)d_in[8];
    const float* cls_final_b  = (const float*)d_in[9];
    const float* reg_conv_w   = (const float*)d_in[10];
    const float* reg_bn_scale = (const float*)d_in[11];
    const float* reg_bn_bias  = (const float*)d_in[12];
    const float* reg_final_w  = (const float*)d_in[13];
    const float* reg_final_b  = (const float*)d_in[14];
    float* out = (float*)d_out;

    float *bufA, *bufB, *wt;
    cudaGetSymbolAddress((void**)&bufA, g_bufA);
    cudaGetSymbolAddress((void**)&bufB, g_bufB);
    cudaGetSymbolAddress((void**)&wt,   g_wt);

    // Fold BN scale into 3x3 weights + transpose. 4,718,592 / 256 = 18,432 CTAs.
    fold_weights_kernel<<<18432, 256>>>(cls_conv_w, cls_bn_scale,
                                        reg_conv_w, reg_bn_scale);

    const int   Hs[5]  = {128, 64, 32, 16, 8};
    const float scs[5] = {8.f, 16.f, 32.f, 64.f, 128.f};

    size_t cls_off[5], reg_off[5], ctr_off[5];
    size_t a = 0;
    for (int l = 0; l < 5; ++l) { cls_off[l] = a; a += (size_t)4 * 80 * Hs[l] * Hs[l]; }
    for (int l = 0; l < 5; ++l) { reg_off[l] = a; a += (size_t)4 * 4  * Hs[l] * Hs[l]; }
    for (int l = 0; l < 5; ++l) { ctr_off[l] = a; a += (size_t)4 * 1  * Hs[l] * Hs[l]; }

    for (int l = 0; l < 5; ++l) {
        const int H = Hs[l], W = Hs[l], HW = H * W;
        for (int head = 0; head < 2; ++head) {
            const float* bias_base = head ? reg_bn_bias : cls_bn_bias;
            float* bufs[2] = {bufA, bufB};
            for (int L = 0; L < 4; ++L) {
                const float* src = (L == 0) ? fpn[l] : bufs[(L + 1) & 1];
                float*       dst = bufs[L & 1];
                const float* wL  = wt + (size_t)(head * 4 + L) * 2304 * 256;
                if (l < 2) {
                    dim3 grid(W / 16, H / 8, 8);     // 4 batch x 2 k-tiles
                    conv3x3_big<<<grid, 256>>>(src, dst, wL, bias_base + L * 256, H, W);
                } else {
                    dim3 grid(W / 8, H / 8, 16);     // 4 batch x 4 k-tiles
                    conv3x3_small<<<grid, 256>>>(src, dst, wL, bias_base + L * 256, H, W);
                }
            }
            const int PB = (4 * HW) / 256;           // always exact
            if (head == 0)
                final_cls_kernel<<<PB, 256>>>(bufB, cls_final_w, cls_final_b,
                                              out + cls_off[l], HW);
            else
                final_reg_kernel<<<PB, 256>>>(bufB, reg_final_w, reg_final_b,
                                              out + reg_off[l], out + ctr_off[l],
                                              HW, scs[l]);
        }
    }
}